// round 13
// baseline (speedup 1.0000x reference)
#include <cuda_runtime.h>
#include <cstdint>

#define BATCH   8
#define NPTS    8192
#define DIM     64
#define SPTS    1024      // NPOINT
#define NS      32        // NSAMPLE
#define MROWS   (BATCH*SPTS*NS)   // 262144
#define NBLK    (MROWS/64)        // 4096 gemm blocks

typedef unsigned long long u64;

// ---------------- f32x2 packed helpers --------------------------------------
__device__ __forceinline__ u64 pack2(float lo, float hi){
  u64 r; asm("mov.b64 %0,{%1,%2};" : "=l"(r) : "f"(lo), "f"(hi)); return r;
}
__device__ __forceinline__ void unpack2(float& lo, float& hi, u64 p){
  asm("mov.b64 {%0,%1},%2;" : "=f"(lo), "=f"(hi) : "l"(p));
}
__device__ __forceinline__ u64 add2(u64 a, u64 b){
  u64 r; asm("add.rn.f32x2 %0,%1,%2;" : "=l"(r) : "l"(a), "l"(b)); return r;
}
__device__ __forceinline__ u64 mul2(u64 a, u64 b){
  u64 r; asm("mul.rn.f32x2 %0,%1,%2;" : "=l"(r) : "l"(a), "l"(b)); return r;
}
__device__ __forceinline__ void fma2(u64& d, u64 a, u64 b){
  asm("fma.rn.f32x2 %0,%1,%2,%0;" : "+l"(d) : "l"(a), "l"(b));
}

// ---------------- scratch ---------------------------------------------------
__device__ int   g_fps_idx[BATCH*SPTS];
__device__ float g_new_xyz[BATCH*SPTS*3];
__device__ int   g_ball[BATCH*SPTS*NS];
__device__ float g_ptsT[BATCH*NPTS*DIM];
__device__ float g_h1[(size_t)MROWS*64];
__device__ float g_h2[(size_t)MROWS*64];
__device__ float g_mx[(size_t)BATCH*SPTS*128];
__device__ float g_mn[(size_t)BATCH*SPTS*128];
__device__ float g_pS [(size_t)128*NBLK];   // channel-major
__device__ float g_pSS[(size_t)128*NBLK];
__device__ float g_scale[128];
__device__ float g_shift[128];

// ---------------- FPS: byte-identical to R11 (proven 1043) ------------------
__global__ __launch_bounds__(1024,1) void fps_kernel(const float* __restrict__ xyz){
  extern __shared__ float sxyz[];            // 3*8192 floats
  __shared__ unsigned swarp[32];
  __shared__ unsigned srev[2];
  const int b   = blockIdx.x;
  const int tid = threadIdx.x;
  const float* xb = xyz + (size_t)b*3*NPTS;
  for (int i=tid; i<3*NPTS; i+=1024) sxyz[i]=xb[i];
  if (tid<2) srev[tid]=0u;
  __syncthreads();

  u64 rx2[4], ry2[4], rz2[4];
  float rdl[4], rdh[4];
#pragma unroll
  for (int j=0;j<4;j++){
    int plo=j*1024+tid, phi=(j+4)*1024+tid;
    rx2[j]=pack2(sxyz[plo],       sxyz[phi]);
    ry2[j]=pack2(sxyz[NPTS+plo],  sxyz[NPTS+phi]);
    rz2[j]=pack2(sxyz[2*NPTS+plo],sxyz[2*NPTS+phi]);
    rdl[j]=1e10f; rdh[j]=1e10f;
  }
  int far=0, p=0;
  const int lane=tid&31, wid=tid>>5;
  const unsigned base = (unsigned)(NPTS-1-tid);

  for (int it=0; it<SPTS; ++it){
    if (tid==0) g_fps_idx[b*SPTS+it]=far;
    const float cx=sxyz[far], cy=sxyz[NPTS+far], cz=sxyz[2*NPTS+far];
    const u64 ncx=pack2(-cx,-cx), ncy=pack2(-cy,-cy), ncz=pack2(-cz,-cz);
    float m=0.f;
#pragma unroll
    for (int j=0;j<4;j++){
      u64 dx=add2(rx2[j],ncx);            // x + (-c) == x - c (IEEE)
      u64 dy=add2(ry2[j],ncy);
      u64 dz=add2(rz2[j],ncz);
      u64 s2=add2(add2(mul2(dx,dx),mul2(dy,dy)),mul2(dz,dz));
      float dl,dh; unpack2(dl,dh,s2);
      float nl=fminf(rdl[j],dl), nh=fminf(rdh[j],dh);
      rdl[j]=nl; rdh[j]=nh;
      m = fmaxf(m, fmaxf(nl,nh));
    }
    const unsigned wbits = __reduce_max_sync(0xffffffffu, __float_as_uint(m));
    if (lane==0) swarp[wid]=wbits;
    __syncthreads();                       // (1) warp maxima ready
    const unsigned vbits = __reduce_max_sync(0xffffffffu, swarp[lane]);
    const float vmax = __uint_as_float(vbits);
    if (wbits==vbits){                     // WARP-UNIFORM guard
      unsigned rev=0u;
#pragma unroll
      for (int j=0;j<4;j++){
        if (rdl[j]==vmax){ unsigned r=base-(unsigned)(j<<10);     rev = r>rev?r:rev; }
        if (rdh[j]==vmax){ unsigned r=base-(unsigned)((j+4)<<10); rev = r>rev?r:rev; }
      }
      rev = __reduce_max_sync(0xffffffffu, rev);
      if (lane==0) atomicMax(&srev[p], rev);
    }
    __syncthreads();                       // (2) index ready
    far = (NPTS-1) - (int)srev[p];
    if (tid==0) srev[p^1]=0u;
    p ^= 1;
  }
}

// ---------------- new_xyz gather + first output section --------------------
__global__ void newxyz_kernel(const float* __restrict__ xyz, float* __restrict__ out){
  int b=blockIdx.x, s=threadIdx.x;
  int idx = g_fps_idx[b*SPTS+s];
#pragma unroll
  for (int d=0; d<3; d++){
    float v = xyz[(size_t)b*3*NPTS + (size_t)d*NPTS + idx];
    g_new_xyz[(b*SPTS+s)*3+d]=v;
    out[(size_t)b*3*SPTS + (size_t)d*SPTS + s]=v;
  }
}

// ---------------- ball query: one warp per query ---------------------------
__global__ void ball_kernel(const float* __restrict__ xyz){
  const int gw   = (blockIdx.x*blockDim.x + threadIdx.x) >> 5;  // 0..8191
  const int lane = threadIdx.x & 31;
  const int wl   = threadIdx.x >> 5;
  const int b = gw >> 10;
  __shared__ int sidx[8][NS];
  const float cx=g_new_xyz[gw*3+0], cy=g_new_xyz[gw*3+1], cz=g_new_xyz[gw*3+2];
  const float* xb = xyz + (size_t)b*3*NPTS;
  unsigned cnt=0;
  for (int basep=0; basep<NPTS; basep+=32){
    int pp = basep+lane;
    float dx=__fsub_rn(cx,xb[pp]);
    float dy=__fsub_rn(cy,xb[NPTS+pp]);
    float dz=__fsub_rn(cz,xb[2*NPTS+pp]);
    float d=__fadd_rn(__fadd_rn(__fmul_rn(dx,dx),__fmul_rn(dy,dy)),__fmul_rn(dz,dz));
    bool in = !(d > 0.04f);
    unsigned mm = __ballot_sync(0xffffffffu, in);
    if (in){
      unsigned r = cnt + __popc(mm & ((1u<<lane)-1u));
      if (r < NS) sidx[wl][r] = pp;
    }
    cnt += __popc(mm);
    if (cnt >= NS) break;
  }
  __syncwarp();
  unsigned c = cnt < NS ? cnt : NS;
  int first = sidx[wl][0];
  int v = (lane < (int)c) ? sidx[wl][lane] : first;
  g_ball[gw*NS + lane] = v;
}

// ---------------- points transpose (B,64,N) -> (B,N,64) --------------------
__global__ void transpose_kernel(const float* __restrict__ pts){
  __shared__ float tile[32][33];
  int b  = blockIdx.z;
  int n0 = blockIdx.x*32;
  int c0 = blockIdx.y*32;
  int tx = threadIdx.x, ty = threadIdx.y;     // 32 x 8
  const float* pb = pts + (size_t)b*DIM*NPTS;
#pragma unroll
  for (int j=0;j<32;j+=8)
    tile[ty+j][tx] = pb[(size_t)(c0+ty+j)*NPTS + n0+tx];
  __syncthreads();
  float* ob = g_ptsT + (size_t)b*NPTS*DIM;
#pragma unroll
  for (int j=0;j<32;j+=8)
    ob[(size_t)(n0+ty+j)*DIM + c0+tx] = tile[tx][ty+j];
}

// ---------------- GEMM: no-splat even/odd-k f32x2, interleaved ownership ----
// Thread owns rows {tm+i*16} and cols {tn+j*TN}.  T = 16*TN, TN = BN/4.
// sA [64][68] m-major, sB [BN][68] n-major — both conflict-free for the
// interleaved mapping (A: phase-broadcast; B: 4*tn mod 32 distinct per phase).
// MODE 0: layer1 — gather A from ptsT/ball/xyz, features [pts64|xyz3|0], W permuted
// MODE 1: layer2 — A = prev H with fused BN+ReLU (K=64)
// MODE 2: layer3 — no H store, + max/min pool epilogue (BN=128, T=512)
template<int K, int BN, int T, int MODE>
__global__ __launch_bounds__(T) void gemm_kernel(const float* __restrict__ A,
    const float* __restrict__ W,
    const float* __restrict__ bias, float* __restrict__ H,
    const float* __restrict__ xyz){
  constexpr bool GATHER = (MODE==0);
  constexpr bool AFF    = (MODE>=1);
  constexpr bool POOL   = (MODE==2);
  constexpr int  TN = BN/4;             // 16 or 32
  extern __shared__ float sm[];
  float* sA    = sm;                    // [64][68] m-major
  float* sB    = sA + 64*68;            // [BN][68] n-major
  float* sbias = sB + BN*68;            // BN
  float* ssc   = sbias + BN;            // 64 (AFF)
  float* ssh   = ssc + 64;
  __shared__ int   sn[64];
  __shared__ float sctr[6];
  const int tid = threadIdx.x;
  const int m0  = blockIdx.x*64;

  for (int o=tid;o<BN;o+=T) sbias[o]=bias[o];
  if (AFF) for (int c=tid;c<64;c+=T){ ssc[c]=g_scale[c]; ssh[c]=g_shift[c]; }
  // B tile (W cols permuted for GATHER feature order [pts|xyz|0])
  for (int idx=tid; idx<BN*68; idx+=T){
    int n=idx/68, c=idx-n*68;
    float v;
    if (GATHER) v = (c<64)? W[n*67 + c+3] : (c<67 ? W[n*67 + (c-64)] : 0.f);
    else        v = (c<64)? W[n*64 + c] : 0.f;
    sB[idx]=v;
  }

  if (GATHER){
    if (tid<64) sn[tid] = g_ball[(size_t)m0 + tid];
    if (tid>=64 && tid<70) sctr[tid-64] = g_new_xyz[(m0>>5)*3 + (tid-64)];
    __syncthreads();
    const int b = blockIdx.x >> 9;      // 512 blocks per batch
    for (int idx=tid; idx<64*16; idx+=T){
      int m = idx>>4, c4 = idx&15;
      int n = sn[m];
      float4 v = *(const float4*)(g_ptsT + ((size_t)b*NPTS + n)*DIM + c4*4);
      *(float4*)&sA[m*68 + c4*4] = v;   // single STS.128, conflict-free
    }
    if (tid<64){
      int n=sn[tid];
      const float* xb = xyz + (size_t)b*3*NPTS;
      const int grp = (tid>>5)*3;
      sA[tid*68+64] = __fsub_rn(xb[n],        sctr[grp+0]);
      sA[tid*68+65] = __fsub_rn(xb[NPTS+n],   sctr[grp+1]);
      sA[tid*68+66] = __fsub_rn(xb[2*NPTS+n], sctr[grp+2]);
      sA[tid*68+67] = 0.f;
    }
  } else {
    __syncthreads();                    // ssc/ssh visible
    const float4* A4 = (const float4*)A;
    for (int idx=tid; idx<64*16; idx+=T){
      int m=idx>>4, c4=idx&15;
      float4 v = A4[(size_t)(m0+m)*16 + c4];
      int cc=c4*4;
      v.x = fmaxf(fmaf(v.x, ssc[cc  ], ssh[cc  ]), 0.f);
      v.y = fmaxf(fmaf(v.y, ssc[cc+1], ssh[cc+1]), 0.f);
      v.z = fmaxf(fmaf(v.z, ssc[cc+2], ssh[cc+2]), 0.f);
      v.w = fmaxf(fmaf(v.w, ssc[cc+3], ssh[cc+3]), 0.f);
      *(float4*)&sA[m*68+cc] = v;       // single STS.128
    }
  }
  __syncthreads();

  // ---- main loop: zero splats; lanes = even/odd k partial sums ----
  const int tm = tid/TN, tn = tid%TN;
  u64 acc[4][4];
#pragma unroll
  for (int i=0;i<4;i++)
#pragma unroll
    for (int j=0;j<4;j++) acc[i][j]=0ull;

#pragma unroll 2
  for (int k=0;k<K;k+=4){
    float4 av[4], bv[4];
#pragma unroll
    for (int i=0;i<4;i++) av[i] = *(const float4*)(sA + (tm+i*16)*68 + k);
#pragma unroll
    for (int j=0;j<4;j++) bv[j] = *(const float4*)(sB + (tn+j*TN)*68 + k);
#pragma unroll
    for (int i=0;i<4;i++){
      u64 a01=((const u64*)&av[i])[0], a23=((const u64*)&av[i])[1];
#pragma unroll
      for (int j=0;j<4;j++){
        fma2(acc[i][j], a01, ((const u64*)&bv[j])[0]);
        fma2(acc[i][j], a23, ((const u64*)&bv[j])[1]);
      }
    }
  }

  float vals[4][4];
#pragma unroll
  for (int i=0;i<4;i++)
#pragma unroll
    for (int j=0;j<4;j++){
      float lo,hi; unpack2(lo,hi,acc[i][j]);
      vals[i][j] = (lo+hi) + sbias[tn+j*TN];
    }

  if (!POOL){
#pragma unroll
    for (int i=0;i<4;i++)
#pragma unroll
      for (int j=0;j<4;j++)
        H[(size_t)(m0+tm+i*16)*BN + tn + j*TN] = vals[i][j];
  }

  // ---- deterministic column sum / sumsq ----
  __syncthreads();
  float* sS  = sm;                      // [BN][16]
  float* sSS = sm + 16*BN;
#pragma unroll
  for (int j=0;j<4;j++){
    int col = tn + j*TN;
    float v0=vals[0][j], v1=vals[1][j], v2=vals[2][j], v3=vals[3][j];
    sS [col*16+tm] = ((v0+v1)+v2)+v3;
    sSS[col*16+tm] = ((v0*v0+v1*v1)+v2*v2)+v3*v3;
  }
  __syncthreads();
  if (tid < BN){
    float s=0.f, ss=0.f;
#pragma unroll
    for (int t=0;t<16;t++){ s+=sS[tid*16+t]; ss+=sSS[tid*16+t]; }
    g_pS [(size_t)tid*NBLK + blockIdx.x] = s;
    g_pSS[(size_t)tid*NBLK + blockIdx.x] = ss;
  }

  if (POOL){
    // rows tm,tm+16 -> sample group 0; rows tm+32,tm+48 -> group 1
#pragma unroll
    for (int grp=0; grp<2; grp++){
      __syncthreads();
#pragma unroll
      for (int j=0;j<4;j++){
        int col = tn + j*TN;
        sS [col*16+tm] = fmaxf(vals[2*grp][j], vals[2*grp+1][j]);
        sSS[col*16+tm] = fminf(vals[2*grp][j], vals[2*grp+1][j]);
      }
      __syncthreads();
      if (tid < BN){
        float mx=-3.4e38f, mn=3.4e38f;
#pragma unroll
        for (int t=0;t<16;t++){ mx=fmaxf(mx,sS[tid*16+t]); mn=fminf(mn,sSS[tid*16+t]); }
        size_t gidx = (size_t)(blockIdx.x*2+grp)*128 + tid;
        g_mx[gidx]=mx; g_mn[gidx]=mn;
      }
    }
  }
}

// ---------------- BN stats: one block per channel ---------------------------
__global__ void bnstats_kernel(const float* __restrict__ g, const float* __restrict__ beta){
  __shared__ float sh[512];
  const int c=blockIdx.x, t=threadIdx.x;   // 256 threads
  float s=0.f, ss=0.f;
  const float* ps  = g_pS  + (size_t)c*NBLK;
  const float* pss = g_pSS + (size_t)c*NBLK;
  for (int i=t;i<NBLK;i+=256){ s+=ps[i]; ss+=pss[i]; }
  sh[t]=s; sh[256+t]=ss; __syncthreads();
  for (int o=128;o>0;o>>=1){
    if (t<o){ sh[t]+=sh[t+o]; sh[256+t]+=sh[256+t+o]; }
    __syncthreads();
  }
  if (t==0){
    const float inv = 1.0f/(float)MROWS;
    float mean = sh[0]*inv;
    float var  = sh[256]*inv - mean*mean;
    float rstd = rsqrtf(var + 1e-5f);
    float sc   = rstd*g[c];
    g_scale[c] = sc;
    g_shift[c] = beta[c] - mean*sc;
  }
}

// ---------------- final pool: norm+relu on pre-reduced max/min -------------
__global__ void pool_kernel(float* __restrict__ out){
  const int gq=blockIdx.x;                   // 0..8191 (b*1024+s)
  const int o =threadIdx.x;                  // 0..127
  const int b=gq>>10, s=gq&1023;
  const float sc=g_scale[o], sh=g_shift[o];
  const float mx=g_mx[(size_t)gq*128+o], mn=g_mn[(size_t)gq*128+o];
  float v = (sc>=0.f)? fmaf(mx,sc,sh) : fmaf(mn,sc,sh);
  out[24576 + (size_t)b*131072 + (size_t)o*1024 + s] = fmaxf(v, 0.f);
}

// ---------------- launch ----------------------------------------------------
extern "C" void kernel_launch(void* const* d_in, const int* in_sizes, int n_in,
                              void* d_out, int out_size){
  (void)in_sizes; (void)n_in; (void)out_size;
  const float* xyz = (const float*)d_in[0];
  const float* pts = (const float*)d_in[1];
  const float* w0  = (const float*)d_in[2];
  const float* b0  = (const float*)d_in[3];
  const float* gg0 = (const float*)d_in[4];
  const float* be0 = (const float*)d_in[5];
  const float* w1  = (const float*)d_in[6];
  const float* b1  = (const float*)d_in[7];
  const float* gg1 = (const float*)d_in[8];
  const float* be1 = (const float*)d_in[9];
  const float* w2  = (const float*)d_in[10];
  const float* b2  = (const float*)d_in[11];
  const float* gg2 = (const float*)d_in[12];
  const float* be2 = (const float*)d_in[13];
  float* out = (float*)d_out;

  // dyn smem (floats): 64*68 + BN*68 + BN (+128 if AFF)
  const int smem1 = (64*68 + 64*68  + 64)*4;        // 35072
  const int smem2 = (64*68 + 64*68  + 64 + 128)*4;  // 35584
  const int smem3 = (64*68 + 128*68 + 128 + 128)*4; // 53248

  cudaFuncSetAttribute(fps_kernel, cudaFuncAttributeMaxDynamicSharedMemorySize, 3*NPTS*4);
  cudaFuncSetAttribute((const void*)gemm_kernel<68,64,256,0>,
                       cudaFuncAttributeMaxDynamicSharedMemorySize, smem1);
  cudaFuncSetAttribute((const void*)gemm_kernel<64,64,256,1>,
                       cudaFuncAttributeMaxDynamicSharedMemorySize, smem2);
  cudaFuncSetAttribute((const void*)gemm_kernel<64,128,512,2>,
                       cudaFuncAttributeMaxDynamicSharedMemorySize, smem3);

  float *pH1,*pH2;
  cudaGetSymbolAddress((void**)&pH1, g_h1);
  cudaGetSymbolAddress((void**)&pH2, g_h2);

  fps_kernel<<<BATCH, 1024, 3*NPTS*4>>>(xyz);
  newxyz_kernel<<<BATCH, SPTS>>>(xyz, out);
  ball_kernel<<<1024, 256>>>(xyz);
  transpose_kernel<<<dim3(NPTS/32, DIM/32, BATCH), dim3(32,8)>>>(pts);

  gemm_kernel<68,64,256,0><<<NBLK, 256, smem1>>>(nullptr, w0, b0, pH1, xyz);
  bnstats_kernel<<<64, 256>>>(gg0, be0);

  gemm_kernel<64,64,256,1><<<NBLK, 256, smem2>>>(pH1, w1, b1, pH2, xyz);
  bnstats_kernel<<<64, 256>>>(gg1, be1);

  gemm_kernel<64,128,512,2><<<NBLK, 512, smem3>>>(pH2, w2, b2, nullptr, xyz);
  bnstats_kernel<<<128, 256>>>(gg2, be2);

  pool_kernel<<<BATCH*SPTS, 128>>>(out);
}